// round 6
// baseline (speedup 1.0000x reference)
#include <cuda_runtime.h>
#include <cstdint>

#define NB   32
#define NQ   300
#define NC   11
#define NT   3200
#define NP   (NB*NQ)      // 9600 predictions
#define PF   20           // floats per pred record in shared
#define PPB  16           // preds per block
#define THR  800          // threads per block; 800*4 = 3200 targets
#define EPSV 1e-6f

// one output element: C = negprob + 5*L1 - 2*GIoU
__device__ __forceinline__ float cost_elem(
    float negprob,
    float pcx, float pcy, float pw, float ph,
    float px0, float py0, float px1, float py1, float pa,
    float tcx, float tcy, float tw, float th,
    float tx0, float ty0, float tx1, float ty1, float ta)
{
    float l1 = fabsf(pcx - tcx) + fabsf(pcy - tcy) + fabsf(pw - tw) + fabsf(ph - th);
    float ix = fminf(px1, tx1) - fmaxf(px0, tx0);
    float iy = fminf(py1, ty1) - fmaxf(py0, ty0);
    ix = fmaxf(ix, 0.f);
    iy = fmaxf(iy, 0.f);
    float inter = ix * iy;
    float uni   = pa + ta - inter;
    float iou   = __fdividef(inter, uni + EPSV);
    float ex = fmaxf(px1, tx1) - fminf(px0, tx0);
    float ey = fmaxf(py1, ty1) - fminf(py0, ty0);
    float areac = ex * ey;                      // enclosing box, always >= 0
    float term  = __fdividef(areac - uni, areac + EPSV);
    float giou  = iou - term;
    return fmaf(-2.f, giou, fmaf(5.f, l1, negprob));
}

__global__ __launch_bounds__(THR, 1) void fused_cost_kernel(
    const float* __restrict__ logits,   // [NP, NC]
    const float* __restrict__ pboxes,   // [NP, 4] cxcywh
    const int*   __restrict__ tlabels,  // [NT]
    const float* __restrict__ tboxes,   // [NT, 4] cxcywh
    float*       __restrict__ out)      // [NP, NT]
{
    __shared__ float sp[PPB * PF];
    const int tid = threadIdx.x;

    // ---- first PPB threads: softmax + box features for this block's preds ----
    if (tid < PPB) {
        const int n = blockIdx.x * PPB + tid;
        const float* l = logits + n * NC;
        float v[NC];
        float m = -1e30f;
#pragma unroll
        for (int c = 0; c < NC; c++) { v[c] = l[c]; m = fmaxf(m, v[c]); }
        float s = 0.f;
#pragma unroll
        for (int c = 0; c < NC; c++) { v[c] = __expf(v[c] - m); s += v[c]; }
        const float inv = __fdividef(1.f, s);
        float* o = sp + tid * PF;
#pragma unroll
        for (int c = 0; c < NC; c++) o[c] = -v[c] * inv;   // NEGATED prob
        const float4 bb = reinterpret_cast<const float4*>(pboxes)[n];
        const float x0 = bb.x - 0.5f * bb.z, y0 = bb.y - 0.5f * bb.w;
        const float x1 = bb.x + 0.5f * bb.z, y1 = bb.y + 0.5f * bb.w;
        o[11] = bb.x; o[12] = bb.y; o[13] = bb.z; o[14] = bb.w;
        o[15] = x0;   o[16] = y0;   o[17] = x1;   o[18] = y1;
        o[19] = (x1 - x0) * (y1 - y0);
    }

    // ---- every thread: features for its 4 consecutive targets (registers) ----
    float tcx[4], tcy[4], tw[4], th[4], tx0[4], ty0[4], tx1[4], ty1[4], ta[4];
    int   lab[4];
    {
        const int t0 = tid * 4;
        const int4 lv = *reinterpret_cast<const int4*>(tlabels + t0);
        lab[0] = lv.x; lab[1] = lv.y; lab[2] = lv.z; lab[3] = lv.w;
#pragma unroll
        for (int j = 0; j < 4; j++) {
            const float4 bb = reinterpret_cast<const float4*>(tboxes)[t0 + j];
            tcx[j] = bb.x; tcy[j] = bb.y; tw[j] = bb.z; th[j] = bb.w;
            tx0[j] = bb.x - 0.5f * bb.z; ty0[j] = bb.y - 0.5f * bb.w;
            tx1[j] = bb.x + 0.5f * bb.z; ty1[j] = bb.y + 0.5f * bb.w;
            ta[j]  = (tx1[j] - tx0[j]) * (ty1[j] - ty0[j]);
        }
    }

    __syncthreads();

    float* obase = out + (size_t)blockIdx.x * (PPB * NT) + (size_t)tid * 4;

#pragma unroll 2
    for (int p = 0; p < PPB; p++) {
        const float* pp = sp + p * PF;           // broadcast LDS
        const float pcx = pp[11], pcy = pp[12], pw = pp[13], ph = pp[14];
        const float px0 = pp[15], py0 = pp[16], px1 = pp[17], py1 = pp[18];
        const float pa  = pp[19];

        float r[4];
#pragma unroll
        for (int j = 0; j < 4; j++) {
            r[j] = cost_elem(pp[lab[j]], pcx, pcy, pw, ph, px0, py0, px1, py1, pa,
                             tcx[j], tcy[j], tw[j], th[j],
                             tx0[j], ty0[j], tx1[j], ty1[j], ta[j]);
        }

        *reinterpret_cast<float4*>(obase + (size_t)p * NT) =
            make_float4(r[0], r[1], r[2], r[3]);   // STG.128
    }
}

extern "C" void kernel_launch(void* const* d_in, const int* in_sizes, int n_in,
                              void* d_out, int out_size) {
    const float* logits  = (const float*)d_in[0];  // [B,Q,C]
    const float* pboxes  = (const float*)d_in[1];  // [B,Q,4]
    const int*   tlabels = (const int*)  d_in[2];  // [T]
    const float* tboxes  = (const float*)d_in[3];  // [T,4]
    float*       out     = (float*)d_out;          // [B,Q,T]

    fused_cost_kernel<<<NP / PPB, THR>>>(logits, pboxes, tlabels, tboxes, out);
}

// round 7
// speedup vs baseline: 1.1686x; 1.1686x over previous
#include <cuda_runtime.h>
#include <cstdint>

#define NB   32
#define NQ   300
#define NC   11
#define NT   3200
#define NP   (NB*NQ)      // 9600 predictions
#define RECF 24           // floats per pred record (96B, 16B-aligned fields)
#define PPB  10           // preds per block -> grid 960 (6.49 waves, low quantization)
#define THR  800          // threads; 800*4 = 3200 targets
#define EPSV 1e-6f

// ---- scratch (no allocations allowed) ----
// pred record: [0..10] -prob, [12..15] 5*cxcywh, [16..19] xyxy, [20] area+eps
__device__ float  g_pred[NP * RECF];
__device__ float4 g_t5[NT];      // 5*(cx,cy,w,h)
__device__ float4 g_txy[NT];     // (x0,y0,x1,y1)
__device__ float2 g_talab[NT];   // (area, bitcast(label))

// ---------------- combined precompute (one launch) ----------------
__global__ void precompute_kernel(const float* __restrict__ logits,
                                  const float* __restrict__ pboxes,
                                  const int*   __restrict__ tlabels,
                                  const float* __restrict__ tboxes) {
    const int i = blockIdx.x * blockDim.x + threadIdx.x;

    if (i < NT) {
        const float4 bb = reinterpret_cast<const float4*>(tboxes)[i];
        const float x0 = bb.x - 0.5f * bb.z, y0 = bb.y - 0.5f * bb.w;
        const float x1 = bb.x + 0.5f * bb.z, y1 = bb.y + 0.5f * bb.w;
        g_t5[i]  = make_float4(5.f * bb.x, 5.f * bb.y, 5.f * bb.z, 5.f * bb.w);
        g_txy[i] = make_float4(x0, y0, x1, y1);
        g_talab[i] = make_float2((x1 - x0) * (y1 - y0),
                                 __int_as_float(tlabels[i]));
    }

    if (i < NP) {
        const float* l = logits + i * NC;
        float v[NC];
        float m = -1e30f;
#pragma unroll
        for (int c = 0; c < NC; c++) { v[c] = l[c]; m = fmaxf(m, v[c]); }
        float s = 0.f;
#pragma unroll
        for (int c = 0; c < NC; c++) { v[c] = __expf(v[c] - m); s += v[c]; }
        const float inv = __fdividef(1.f, s);
        float* o = g_pred + i * RECF;
#pragma unroll
        for (int c = 0; c < NC; c++) o[c] = -v[c] * inv;   // NEGATED prob
        const float4 bb = reinterpret_cast<const float4*>(pboxes)[i];
        const float x0 = bb.x - 0.5f * bb.z, y0 = bb.y - 0.5f * bb.w;
        const float x1 = bb.x + 0.5f * bb.z, y1 = bb.y + 0.5f * bb.w;
        o[12] = 5.f * bb.x; o[13] = 5.f * bb.y; o[14] = 5.f * bb.z; o[15] = 5.f * bb.w;
        o[16] = x0;  o[17] = y0;  o[18] = x1;  o[19] = y1;
        o[20] = (x1 - x0) * (y1 - y0) + EPSV;              // area + eps (folded)
    }
}

// ---------------- hot cost kernel ----------------
__global__ __launch_bounds__(THR, 1) void cost_kernel(float* __restrict__ out) {
    __shared__ float sp[PPB * RECF];
    const int tid = threadIdx.x;

    // stage PPB pred records (coalesced)
    for (int i = tid; i < PPB * RECF; i += THR)
        sp[i] = g_pred[blockIdx.x * (PPB * RECF) + i];

    // 4 consecutive targets per thread, resident in registers
    float t5x[4], t5y[4], t5w[4], t5h[4];
    float tx0[4], ty0[4], tx1[4], ty1[4], ta[4];
    int   labi[4];                                   // element index into sp record
    {
        const int t0 = tid * 4;
#pragma unroll
        for (int j = 0; j < 4; j++) {
            const float4 a = g_t5[t0 + j];
            t5x[j] = a.x; t5y[j] = a.y; t5w[j] = a.z; t5h[j] = a.w;
            const float4 b = g_txy[t0 + j];
            tx0[j] = b.x; ty0[j] = b.y; tx1[j] = b.z; ty1[j] = b.w;
            const float2 c = g_talab[t0 + j];
            ta[j]   = c.x;
            labi[j] = __float_as_int(c.y);
        }
    }

    __syncthreads();

    const int obase = blockIdx.x * (PPB * NT) + tid * 4;   // fits in int32

#pragma unroll
    for (int p = 0; p < PPB; p++) {
        // pred features: 2x LDS.128 + 1x LDS.32, broadcast across warp
        const float4 c5 = *reinterpret_cast<const float4*>(sp + p * RECF + 12);
        const float4 xy = *reinterpret_cast<const float4*>(sp + p * RECF + 16);
        const float paeps = sp[p * RECF + 20];

        float rr[4];
#pragma unroll
        for (int j = 0; j < 4; j++) {
            // 5*L1 (boxes pre-scaled by 5)
            float l1 = fabsf(c5.x - t5x[j]) + fabsf(c5.y - t5y[j])
                     + fabsf(c5.z - t5w[j]) + fabsf(c5.w - t5h[j]);
            // intersection
            float ix = fmaxf(fminf(xy.z, tx1[j]) - fmaxf(xy.x, tx0[j]), 0.f);
            float iy = fmaxf(fminf(xy.w, ty1[j]) - fmaxf(xy.y, ty0[j]), 0.f);
            float inter = ix * iy;
            // d1 = union + eps  (eps folded into paeps)
            float d1 = paeps + ta[j] - inter;
            float iou = __fdividef(inter, d1);
            // enclosing box (always >= 0 for valid boxes, clamp dropped)
            float ex = fmaxf(xy.z, tx1[j]) - fminf(xy.x, tx0[j]);
            float ey = fmaxf(xy.w, ty1[j]) - fminf(xy.y, ty0[j]);
            float d2   = fmaf(ex, ey, EPSV);     // area_c + eps
            float num2 = d2 - d1;                // == area_c - union (exact)
            float term = __fdividef(num2, d2);
            // C = negprob + 5*L1 - 2*iou + 2*term
            float acc = l1 + sp[labi[j] + p * RECF];   // LDS [Rlab + imm]
            acc = fmaf(-2.f, iou, acc);
            rr[j] = fmaf(2.f, term, acc);
        }

        *reinterpret_cast<float4*>(out + (obase + p * NT)) =
            make_float4(rr[0], rr[1], rr[2], rr[3]);     // STG.128, imm offset
    }
}

extern "C" void kernel_launch(void* const* d_in, const int* in_sizes, int n_in,
                              void* d_out, int out_size) {
    const float* logits  = (const float*)d_in[0];  // [B,Q,C]
    const float* pboxes  = (const float*)d_in[1];  // [B,Q,4]
    const int*   tlabels = (const int*)  d_in[2];  // [T]
    const float* tboxes  = (const float*)d_in[3];  // [T,4]
    float*       out     = (float*)d_out;          // [B,Q,T]

    precompute_kernel<<<NP / 128, 128>>>(logits, pboxes, tlabels, tboxes);
    cost_kernel<<<NP / PPB, THR>>>(out);
}

// round 8
// speedup vs baseline: 1.5726x; 1.3457x over previous
#include <cuda_runtime.h>
#include <cstdint>

#define NB   32
#define NQ   300
#define NC   11
#define NT   3200
#define NP   (NB*NQ)      // 9600 predictions
#define PF   20           // floats per pred record
#define PPB  16           // preds per block in main kernel
#define THR  800          // threads per block (25 warps); 800*4 = 3200 targets
#define EPSV 1e-6f

// ---- scratch (no allocations allowed) ----
__device__ float g_pred[NP * PF];   // [0..10] -prob, [11..14] cxcywh, [15..18] xyxy, [19] area+eps
__device__ float g_tcx[NT], g_tcy[NT], g_tw[NT], g_th[NT];
__device__ float g_tx0[NT], g_ty0[NT], g_tx1[NT], g_ty1[NT], g_ta[NT];
__device__ int   g_tlab[NT];

// ---------------- combined precompute (single launch, 64-thr blocks) ----------------
__global__ void precompute_kernel(const float* __restrict__ logits,
                                  const float* __restrict__ pboxes,
                                  const int*   __restrict__ tlabels,
                                  const float* __restrict__ tboxes) {
    const int i = blockIdx.x * blockDim.x + threadIdx.x;

    if (i < NT) {
        float cx = tboxes[i*4+0], cy = tboxes[i*4+1], w = tboxes[i*4+2], h = tboxes[i*4+3];
        float x0 = cx - 0.5f*w, y0 = cy - 0.5f*h, x1 = cx + 0.5f*w, y1 = cy + 0.5f*h;
        g_tcx[i] = cx; g_tcy[i] = cy; g_tw[i] = w;  g_th[i] = h;
        g_tx0[i] = x0; g_ty0[i] = y0; g_tx1[i] = x1; g_ty1[i] = y1;
        g_ta[i]  = (x1 - x0) * (y1 - y0);
        g_tlab[i] = tlabels[i];
    }

    if (i < NP) {
        const float* l = logits + i * NC;
        float v[NC];
        float m = -1e30f;
#pragma unroll
        for (int c = 0; c < NC; c++) { v[c] = l[c]; m = fmaxf(m, v[c]); }
        float s = 0.f;
#pragma unroll
        for (int c = 0; c < NC; c++) { v[c] = __expf(v[c] - m); s += v[c]; }
        float inv = __fdividef(1.f, s);
        float* o = g_pred + i * PF;
#pragma unroll
        for (int c = 0; c < NC; c++) o[c] = -v[c] * inv;   // store NEGATED prob
        float cx = pboxes[i*4+0], cy = pboxes[i*4+1], w = pboxes[i*4+2], h = pboxes[i*4+3];
        float x0 = cx - 0.5f*w, y0 = cy - 0.5f*h, x1 = cx + 0.5f*w, y1 = cy + 0.5f*h;
        o[11] = cx; o[12] = cy; o[13] = w;  o[14] = h;
        o[15] = x0; o[16] = y0; o[17] = x1; o[18] = y1;
        o[19] = (x1 - x0) * (y1 - y0) + EPSV;              // area + eps (folded)
    }
}

// one output element: C = negprob + 5*L1 - 2*GIoU
// diet: enclosing box via min/max-sum identity; eps pre-folded into both denominators
__device__ __forceinline__ float cost_elem(
    float negprob,
    float pcx, float pcy, float pw, float ph,
    float px0, float py0, float px1, float py1, float paeps,
    float tcx, float tcy, float tw, float th,
    float tx0, float ty0, float tx1, float ty1, float ta)
{
    float l1 = fabsf(pcx - tcx) + fabsf(pcy - tcy) + fabsf(pw - tw) + fabsf(ph - th);
    float mnx = fminf(px1, tx1), mxx = fmaxf(px0, tx0);
    float mny = fminf(py1, ty1), mxy = fmaxf(py0, ty0);
    float ixr = mnx - mxx, iyr = mny - mxy;      // unclamped extents
    float ix = fmaxf(ixr, 0.f), iy = fmaxf(iyr, 0.f);
    float inter = ix * iy;
    float d1  = paeps + ta - inter;              // union + eps (eps folded)
    float iou = __fdividef(inter, d1);
    // enclosing extents via identity: max(a,b)+min(a,b) = a+b
    float ex = (pw + tw) - ixr;
    float ey = (ph + th) - iyr;
    float d2   = fmaf(ex, ey, EPSV);             // area_c + eps
    float term = __fdividef(d2 - d1, d2);        // (area_c - union)/(area_c + eps), exact
    float giou = iou - term;
    return fmaf(-2.f, giou, fmaf(5.f, l1, negprob));
}

// ---------------- main cost kernel (R1 structure, unchanged) ----------------
__global__ __launch_bounds__(THR, 1) void cost_kernel(float* __restrict__ out) {
    __shared__ float sp[PPB * PF];
    const int tid = threadIdx.x;

    // stage PPB pred records into shared (contiguous AoS block -> coalesced)
    for (int i = tid; i < PPB * PF; i += THR)
        sp[i] = g_pred[(size_t)blockIdx.x * (PPB * PF) + i];

    // 4 consecutive targets per thread, resident in registers
    const float4 tcx = reinterpret_cast<const float4*>(g_tcx)[tid];
    const float4 tcy = reinterpret_cast<const float4*>(g_tcy)[tid];
    const float4 tw  = reinterpret_cast<const float4*>(g_tw )[tid];
    const float4 th  = reinterpret_cast<const float4*>(g_th )[tid];
    const float4 tx0 = reinterpret_cast<const float4*>(g_tx0)[tid];
    const float4 ty0 = reinterpret_cast<const float4*>(g_ty0)[tid];
    const float4 tx1 = reinterpret_cast<const float4*>(g_tx1)[tid];
    const float4 ty1 = reinterpret_cast<const float4*>(g_ty1)[tid];
    const float4 ta  = reinterpret_cast<const float4*>(g_ta )[tid];
    const int4  lab  = reinterpret_cast<const int4 *>(g_tlab)[tid];

    __syncthreads();

    float* obase = out + (size_t)blockIdx.x * (PPB * NT) + (size_t)tid * 4;

#pragma unroll 2
    for (int p = 0; p < PPB; p++) {
        const float* pp = sp + p * PF;           // broadcast LDS
        const float pcx = pp[11], pcy = pp[12], pw = pp[13], ph = pp[14];
        const float px0 = pp[15], py0 = pp[16], px1 = pp[17], py1 = pp[18];
        const float pa  = pp[19];                // area + eps

        float4 r;
        r.x = cost_elem(pp[lab.x], pcx, pcy, pw, ph, px0, py0, px1, py1, pa,
                        tcx.x, tcy.x, tw.x, th.x, tx0.x, ty0.x, tx1.x, ty1.x, ta.x);
        r.y = cost_elem(pp[lab.y], pcx, pcy, pw, ph, px0, py0, px1, py1, pa,
                        tcx.y, tcy.y, tw.y, th.y, tx0.y, ty0.y, tx1.y, ty1.y, ta.y);
        r.z = cost_elem(pp[lab.z], pcx, pcy, pw, ph, px0, py0, px1, py1, pa,
                        tcx.z, tcy.z, tw.z, th.z, tx0.z, ty0.z, tx1.z, ty1.z, ta.z);
        r.w = cost_elem(pp[lab.w], pcx, pcy, pw, ph, px0, py0, px1, py1, pa,
                        tcx.w, tcy.w, tw.w, th.w, tx0.w, ty0.w, tx1.w, ty1.w, ta.w);

        *reinterpret_cast<float4*>(obase + (size_t)p * NT) = r;   // STG.128
    }
}

extern "C" void kernel_launch(void* const* d_in, const int* in_sizes, int n_in,
                              void* d_out, int out_size) {
    const float* logits  = (const float*)d_in[0];  // [B,Q,C]
    const float* pboxes  = (const float*)d_in[1];  // [B,Q,4]
    const int*   tlabels = (const int*)  d_in[2];  // [T]
    const float* tboxes  = (const float*)d_in[3];  // [T,4]
    float*       out     = (float*)d_out;          // [B,Q,T]

    precompute_kernel<<<NP / 64, 64>>>(logits, pboxes, tlabels, tboxes);
    cost_kernel<<<NP / PPB, THR>>>(out);
}

// round 9
// speedup vs baseline: 1.8057x; 1.1482x over previous
#include <cuda_runtime.h>
#include <cstdint>

#define NB   32
#define NQ   300
#define NC   11
#define NT   3200
#define NP   (NB*NQ)      // 9600 predictions
#define PF   20           // floats per pred record (stride kept from proven kernel)
#define PPB  16           // preds per block in main kernel
#define THR  800          // threads per block (25 warps); 800*4 = 3200 targets
#define EPSV 1e-6f

// ---- scratch (no allocations allowed) ----
// pred record: [0..10] (2 - prob_c), [11]=cx, [12]=cy, [13]=w/2, [14]=h/2, [15]=area+eps
__device__ float g_pred[NP * PF];
__device__ float g_tcx[NT], g_tcy[NT], g_tw2[NT], g_th2[NT], g_ta[NT];
__device__ int   g_tlab[NT];

// ---------------- combined precompute (single launch) ----------------
__global__ void precompute_kernel(const float* __restrict__ logits,
                                  const float* __restrict__ pboxes,
                                  const int*   __restrict__ tlabels,
                                  const float* __restrict__ tboxes) {
    const int i = blockIdx.x * blockDim.x + threadIdx.x;

    if (i < NT) {
        float cx = tboxes[i*4+0], cy = tboxes[i*4+1];
        float w2 = 0.5f * tboxes[i*4+2], h2 = 0.5f * tboxes[i*4+3];
        g_tcx[i] = cx; g_tcy[i] = cy; g_tw2[i] = w2; g_th2[i] = h2;
        g_ta[i]  = 4.f * w2 * h2;          // w*h (exact: w=2*w2)
        g_tlab[i] = tlabels[i];
    }

    if (i < NP) {
        const float* l = logits + i * NC;
        float v[NC];
        float m = -1e30f;
#pragma unroll
        for (int c = 0; c < NC; c++) { v[c] = l[c]; m = fmaxf(m, v[c]); }
        float s = 0.f;
#pragma unroll
        for (int c = 0; c < NC; c++) { v[c] = __expf(v[c] - m); s += v[c]; }
        float inv = __fdividef(1.f, s);
        float* o = g_pred + i * PF;
#pragma unroll
        for (int c = 0; c < NC; c++) o[c] = fmaf(-v[c], inv, 2.f);  // 2 - prob (class + giou const folded)
        float cx = pboxes[i*4+0], cy = pboxes[i*4+1];
        float w2 = 0.5f * pboxes[i*4+2], h2 = 0.5f * pboxes[i*4+3];
        o[11] = cx; o[12] = cy; o[13] = w2; o[14] = h2;
        o[15] = 4.f * w2 * h2 + EPSV;      // area + eps (folded)
    }
}

// one output element:
//   C = (2 - prob) + 5*L1 - 2*(inter*d2 + d1^2)/(d1*d2)
// where d1 = union + eps, d2 = area_c + eps (exact reformulation of class/L1/GIoU cost)
__device__ __forceinline__ float cost_elem(
    float spval,
    float pcx, float pcy, float pw2, float ph2, float paeps,
    float tcx, float tcy, float tw2, float th2, float ta)
{
    // shared differences (feed both L1 and the interval identities)
    float adx = fabsf(pcx - tcx), ady = fabsf(pcy - tcy);
    float adw = fabsf(pw2 - tw2), adh = fabsf(ph2 - th2);
    float l1a = adx + ady;
    float l1b = adw + adh;                     // contributes 2x to L1 (half-widths)
    // per-axis: sum of half-widths and the binding max
    float sw = pw2 + tw2,        sh = ph2 + th2;
    float mx = fmaxf(adx, adw),  my = fmaxf(ady, adh);
    // intersection extent (unclamped) and enclosing extent, via min/max identities
    float ixr = sw - mx,         iyr = sh - my;
    float ex  = sw + mx,         ey  = sh + my;
    float ix = fmaxf(ixr, 0.f),  iy = fmaxf(iyr, 0.f);
    float inter = ix * iy;
    float d1 = (paeps + ta) - inter;           // union + eps
    float d2 = fmaf(ex, ey, EPSV);             // area_c + eps
    float num = fmaf(inter, d2, d1 * d1);      // inter*d2 + d1^2
    float den = d1 * d2;
    float acc = fmaf(5.f, l1a, spval);
    acc = fmaf(10.f, l1b, acc);                // + 5*L1 total
    float q = __fdividef(num, den);
    return fmaf(-2.f, q, acc);
}

// ---------------- main cost kernel (proven schedule) ----------------
__global__ __launch_bounds__(THR, 1) void cost_kernel(float* __restrict__ out) {
    __shared__ float sp[PPB * PF];
    const int tid = threadIdx.x;

    // stage PPB pred records into shared (contiguous -> coalesced)
    for (int i = tid; i < PPB * PF; i += THR)
        sp[i] = g_pred[(size_t)blockIdx.x * (PPB * PF) + i];

    // 4 consecutive targets per thread, resident in registers (24 regs total)
    const float4 tcx = reinterpret_cast<const float4*>(g_tcx)[tid];
    const float4 tcy = reinterpret_cast<const float4*>(g_tcy)[tid];
    const float4 tw2 = reinterpret_cast<const float4*>(g_tw2)[tid];
    const float4 th2 = reinterpret_cast<const float4*>(g_th2)[tid];
    const float4 ta  = reinterpret_cast<const float4*>(g_ta )[tid];
    const int4  lab  = reinterpret_cast<const int4 *>(g_tlab)[tid];

    __syncthreads();

    float* obase = out + (size_t)blockIdx.x * (PPB * NT) + (size_t)tid * 4;

#pragma unroll 2
    for (int p = 0; p < PPB; p++) {
        const float* pp = sp + p * PF;         // broadcast LDS
        const float pcx = pp[11], pcy = pp[12], pw2 = pp[13], ph2 = pp[14];
        const float paeps = pp[15];

        float4 r;
        r.x = cost_elem(pp[lab.x], pcx, pcy, pw2, ph2, paeps,
                        tcx.x, tcy.x, tw2.x, th2.x, ta.x);
        r.y = cost_elem(pp[lab.y], pcx, pcy, pw2, ph2, paeps,
                        tcx.y, tcy.y, tw2.y, th2.y, ta.y);
        r.z = cost_elem(pp[lab.z], pcx, pcy, pw2, ph2, paeps,
                        tcx.z, tcy.z, tw2.z, th2.z, ta.z);
        r.w = cost_elem(pp[lab.w], pcx, pcy, pw2, ph2, paeps,
                        tcx.w, tcy.w, tw2.w, th2.w, ta.w);

        *reinterpret_cast<float4*>(obase + (size_t)p * NT) = r;   // STG.128
    }
}

extern "C" void kernel_launch(void* const* d_in, const int* in_sizes, int n_in,
                              void* d_out, int out_size) {
    const float* logits  = (const float*)d_in[0];  // [B,Q,C]
    const float* pboxes  = (const float*)d_in[1];  // [B,Q,4]
    const int*   tlabels = (const int*)  d_in[2];  // [T]
    const float* tboxes  = (const float*)d_in[3];  // [T,4]
    float*       out     = (float*)d_out;          // [B,Q,T]

    precompute_kernel<<<NP / 64, 64>>>(logits, pboxes, tlabels, tboxes);
    cost_kernel<<<NP / PPB, THR>>>(out);
}

// round 14
// speedup vs baseline: 1.8412x; 1.0197x over previous
#include <cuda_runtime.h>
#include <cstdint>

#define NB   32
#define NQ   300
#define NC   11
#define NT   3200
#define NP   (NB*NQ)        // 9600 predictions
#define PF   16             // floats per pred record: [0..10]=2-prob, 11=cx,12=cy,13=w/2,14=h/2,15=area+eps
#define PPB  4              // preds per tile (fine-grained for load balance)
#define NTILES (NP/PPB)     // 2400
#define GRD  148            // persistent: one block per SM
#define THR  800            // 25 warps; 800*4 = 3200 targets
#define EPSV 1e-6f

// ---- scratch (no allocations allowed) ----
__device__ float g_pred[NP * PF];

// ---------------- precompute: pred records only ----------------
__global__ void precompute_kernel(const float* __restrict__ logits,
                                  const float* __restrict__ pboxes) {
    const int i = blockIdx.x * blockDim.x + threadIdx.x;
    if (i >= NP) return;
    const float* l = logits + i * NC;
    float v[NC];
    float m = -1e30f;
#pragma unroll
    for (int c = 0; c < NC; c++) { v[c] = l[c]; m = fmaxf(m, v[c]); }
    float s = 0.f;
#pragma unroll
    for (int c = 0; c < NC; c++) { v[c] = __expf(v[c] - m); s += v[c]; }
    float inv = __fdividef(1.f, s);
    float* o = g_pred + i * PF;
#pragma unroll
    for (int c = 0; c < NC; c++) o[c] = fmaf(-v[c], inv, 2.f);   // 2 - prob (giou const folded)
    const float4 bb = reinterpret_cast<const float4*>(pboxes)[i];
    float w2 = 0.5f * bb.z, h2 = 0.5f * bb.w;
    o[11] = bb.x; o[12] = bb.y; o[13] = w2; o[14] = h2;
    o[15] = bb.z * bb.w + EPSV;                                  // area + eps
}

// one output element (validated R9 math):
//   C = (2 - prob) + 5*L1 - 2*(inter*d2 + d1^2)/(d1*d2)
__device__ __forceinline__ float cost_elem(
    float spval,
    float pcx, float pcy, float pw2, float ph2, float paeps,
    float tcx, float tcy, float tw2, float th2, float ta)
{
    float adx = fabsf(pcx - tcx), ady = fabsf(pcy - tcy);
    float adw = fabsf(pw2 - tw2), adh = fabsf(ph2 - th2);
    float l1a = adx + ady;
    float l1b = adw + adh;
    float sw = pw2 + tw2,        sh = ph2 + th2;
    float mx = fmaxf(adx, adw),  my = fmaxf(ady, adh);
    float ixr = sw - mx,         iyr = sh - my;
    float ex  = sw + mx,         ey  = sh + my;
    float ix = fmaxf(ixr, 0.f),  iy = fmaxf(iyr, 0.f);
    float inter = ix * iy;
    float d1 = (paeps + ta) - inter;
    float d2 = fmaf(ex, ey, EPSV);
    float num = fmaf(inter, d2, d1 * d1);
    float den = d1 * d2;
    float acc = fmaf(5.f, l1a, spval);
    acc = fmaf(10.f, l1b, acc);
    float q = __fdividef(num, den);
    return fmaf(-2.f, q, acc);
}

// ---------------- persistent cost kernel ----------------
__global__ __launch_bounds__(THR, 1) void cost_kernel(
    const int*   __restrict__ tlabels,
    const float* __restrict__ tboxes,
    float*       __restrict__ out)
{
    __shared__ float sp[2][PPB * PF];       // double-buffered pred tiles (512 B)
    const int tid = threadIdx.x;

    // ---- prologue: 4 consecutive targets per thread, resident in registers ----
    float tcx[4], tcy[4], tw2[4], th2[4], ta[4];
    int   lab[4];
    {
        const int t0 = tid * 4;
        const int4 lv = *reinterpret_cast<const int4*>(tlabels + t0);
        lab[0] = lv.x; lab[1] = lv.y; lab[2] = lv.z; lab[3] = lv.w;
#pragma unroll
        for (int j = 0; j < 4; j++) {
            const float4 bb = reinterpret_cast<const float4*>(tboxes)[t0 + j];
            tcx[j] = bb.x;         tcy[j] = bb.y;
            tw2[j] = 0.5f * bb.z;  th2[j] = 0.5f * bb.w;
            ta[j]  = bb.z * bb.w;
        }
    }

    // stage first tile
    int tile = blockIdx.x;
    if (tid < PPB * PF)
        sp[0][tid] = g_pred[tile * (PPB * PF) + tid];
    __syncthreads();

    int nb = 0;
    for (; tile < NTILES; tile += GRD) {
        // prefetch next tile into the other buffer (no hazard: disjoint buffers)
        const int nxt = tile + GRD;
        if (nxt < NTILES && tid < PPB * PF)
            sp[nb ^ 1][tid] = g_pred[nxt * (PPB * PF) + tid];

        float* obase = out + (size_t)tile * (PPB * NT) + (size_t)tid * 4;
        const float* buf = sp[nb];

#pragma unroll 2
        for (int p = 0; p < PPB; p++) {
            const float* pp = buf + p * PF;                 // broadcast LDS
            const float pcx = pp[11], pcy = pp[12], pw2 = pp[13], ph2 = pp[14];
            const float paeps = pp[15];

            float4 r;
            r.x = cost_elem(pp[lab[0]], pcx, pcy, pw2, ph2, paeps,
                            tcx[0], tcy[0], tw2[0], th2[0], ta[0]);
            r.y = cost_elem(pp[lab[1]], pcx, pcy, pw2, ph2, paeps,
                            tcx[1], tcy[1], tw2[1], th2[1], ta[1]);
            r.z = cost_elem(pp[lab[2]], pcx, pcy, pw2, ph2, paeps,
                            tcx[2], tcy[2], tw2[2], th2[2], ta[2]);
            r.w = cost_elem(pp[lab[3]], pcx, pcy, pw2, ph2, paeps,
                            tcx[3], tcy[3], tw2[3], th2[3], ta[3]);

            *reinterpret_cast<float4*>(obase + (size_t)p * NT) = r;   // STG.128
        }

        __syncthreads();   // next buffer fully staged; current fully consumed
        nb ^= 1;
    }
}

extern "C" void kernel_launch(void* const* d_in, const int* in_sizes, int n_in,
                              void* d_out, int out_size) {
    const float* logits  = (const float*)d_in[0];  // [B,Q,C]
    const float* pboxes  = (const float*)d_in[1];  // [B,Q,4]
    const int*   tlabels = (const int*)  d_in[2];  // [T]
    const float* tboxes  = (const float*)d_in[3];  // [T,4]
    float*       out     = (float*)d_out;          // [B,Q,T]

    precompute_kernel<<<NP / 64, 64>>>(logits, pboxes);
    cost_kernel<<<GRD, THR>>>(tlabels, tboxes, out);
}